// round 6
// baseline (speedup 1.0000x reference)
#include <cuda_runtime.h>
#include <cuda_fp16.h>
#include <cstdint>

#define DI __device__ __forceinline__

static const int QL  = 128;
static const int VL  = 2048;
static const int HID = 1024;

// ---------------------------------------------------------------------------
// Scratch (device globals; no runtime allocation allowed). fp16 operands.
// ---------------------------------------------------------------------------
__device__ uint16_t s_q_h[4194304],  s_q_l[4194304];    // split q
__device__ uint16_t s_v_h[67108864];                    // v hi only (1-pass A)
__device__ uint16_t s_Wq_h[1048576];                    // Wq hi (B-side only)
__device__ uint16_t s_Wv_h[1048576];                    // Wv hi
__device__ uint16_t g_qh_h[4194304], g_qh_l[4194304];   // qp result [n][q][d]
__device__ uint16_t g_vh_h[67108864];                   // vp result [n][v][d]
__device__ uint16_t g_vhT_h[67108864];                  // vp result [n][d][v]
__device__ float g_A0[128], g_A1[128], g_A2[128], g_Cc[128];

// ---------------------------------------------------------------------------
DI uint32_t smem_u32(const void* p) {
    uint32_t a;
    asm("{ .reg .u64 t; cvta.to.shared.u64 t, %1; cvt.u32.u64 %0, t; }" : "=r"(a) : "l"(p));
    return a;
}

DI uint32_t sp2h(float a, float b, uint32_t& lo) {
    __half2 h = __floats2half2_rn(a, b);
    float2 f = __half22float2(h);
    __half2 l = __floats2half2_rn(a - f.x, b - f.y);
    lo = *(uint32_t*)&l;
    return *(uint32_t*)&h;
}
DI uint32_t pk2h(float a, float b) {
    __half2 h = __floats2half2_rn(a, b);
    return *(uint32_t*)&h;
}

DI void ldm4(uint32_t* r, uint32_t a) {
    asm volatile("ldmatrix.sync.aligned.m8n8.x4.shared.b16 {%0,%1,%2,%3}, [%4];"
        : "=r"(r[0]), "=r"(r[1]), "=r"(r[2]), "=r"(r[3]) : "r"(a));
}

DI void mma16816(float* d, const uint32_t* a, uint32_t b0, uint32_t b1) {
    asm volatile("mma.sync.aligned.m16n8k16.row.col.f32.f16.f16.f32 "
        "{%0,%1,%2,%3},{%4,%5,%6,%7},{%8,%9},{%0,%1,%2,%3};"
        : "+f"(d[0]), "+f"(d[1]), "+f"(d[2]), "+f"(d[3])
        : "r"(a[0]), "r"(a[1]), "r"(a[2]), "r"(a[3]), "r"(b0), "r"(b1));
}

DI void cp16(uint32_t dst, const void* src) {
    asm volatile("cp.async.cg.shared.global [%0], [%1], 16;" :: "r"(dst), "l"(src));
}
#define CP_COMMIT() asm volatile("cp.async.commit_group;" ::: "memory")
#define CP_WAIT2()  asm volatile("cp.async.wait_group 2;"  ::: "memory")
#define CP_WAIT3()  asm volatile("cp.async.wait_group 3;"  ::: "memory")
#define CP_WAIT1()  asm volatile("cp.async.wait_group 1;"  ::: "memory")

static const int TILE_B = 10240;

// 2-pass mma on one 32-K chunk: (Ah + Al) * Bh. 80B-pitch tiles.
DI void chunk2(uint32_t smb, uint32_t aH0, uint32_t aL0, uint32_t b0,
               int lane, int wm0, int wn0, float (&acc)[2][8][4]) {
#pragma unroll
    for (int ks = 0; ks < 2; ks++) {
        const uint32_t rowsel = (uint32_t)(lane & 15) * 80
                              + (uint32_t)((lane >> 4) + ks * 2) * 16;
        uint32_t aH[2][4], aL[2][4], bH[4][4];
#pragma unroll
        for (int mt = 0; mt < 2; mt++) {
            ldm4(aH[mt], smb + aH0 + (uint32_t)(wm0 + mt * 16) * 80 + rowsel);
            ldm4(aL[mt], smb + aL0 + (uint32_t)(wm0 + mt * 16) * 80 + rowsel);
        }
#pragma unroll
        for (int g = 0; g < 4; g++)
            ldm4(bH[g], smb + b0 + (uint32_t)(wn0 + g * 16) * 80 + rowsel);
#pragma unroll
        for (int mt = 0; mt < 2; mt++)
#pragma unroll
            for (int g = 0; g < 4; g++) {
                mma16816(acc[mt][2 * g],     aH[mt], bH[g][0], bH[g][2]);
                mma16816(acc[mt][2 * g + 1], aH[mt], bH[g][1], bH[g][3]);
            }
#pragma unroll
        for (int mt = 0; mt < 2; mt++)
#pragma unroll
            for (int g = 0; g < 4; g++) {
                mma16816(acc[mt][2 * g],     aL[mt], bH[g][0], bH[g][2]);
                mma16816(acc[mt][2 * g + 1], aL[mt], bH[g][1], bH[g][3]);
            }
    }
}

// ---------------------------------------------------------------------------
// Projection GEMMs (as round 5)
// MODE 0: qp = q@Wq^T + bq          -> g_qh_h/l        grid(8, 32)
// MODE 1: vp = v@Wv^T + bias + loc  -> g_vh_h, g_vhT_h grid(8, 512)  (A 1-pass)
// ---------------------------------------------------------------------------
template <int MODE>
__global__ void __launch_bounds__(256)
mma_gemm(const float* __restrict__ biasv, const float* __restrict__ la)
{
    extern __shared__ char sm[];
    const uint32_t smb = smem_u32(sm);
    const int t = threadIdx.x, lane = t & 31, w = t >> 5;
    const int wm0 = (w & 3) * 32, wn0 = (w >> 2) * 64;

    constexpr int NC  = HID / 32;
    constexpr int NPA = (MODE == 1) ? 1 : 2;
    constexpr int NT  = (MODE == 1) ? 2 : 3;
    constexpr int BUF = NT * TILE_B;
    constexpr uint32_t BOFF = (uint32_t)(NT - 1) * TILE_B;

    const uint16_t *Ah, *Al = nullptr, *Bh;
    if (MODE == 0) {
        size_t ao = (size_t)blockIdx.y * 128 * HID, bo = (size_t)blockIdx.x * 128 * HID;
        Ah = s_q_h + ao; Al = s_q_l + ao; Bh = s_Wq_h + bo;
    } else {
        size_t ao = (size_t)blockIdx.y * 128 * HID, bo = (size_t)blockIdx.x * 128 * HID;
        Ah = s_v_h + ao; Bh = s_Wv_h + bo;
    }

    float acc[2][8][4];
#pragma unroll
    for (int i = 0; i < 2; i++)
#pragma unroll
        for (int j = 0; j < 8; j++)
#pragma unroll
            for (int k = 0; k < 4; k++) acc[i][j][k] = 0.f;

    auto cp_chunk = [&](int buf, int c) {
        uint32_t sb = smb + buf * BUF;
#pragma unroll
        for (int i = 0; i < NT * 2; i++) {
            int idx = t + 256 * i;
            int tile = idx >> 9, r = (idx >> 2) & 127, s = idx & 3;
            const uint16_t* base; uint32_t doff;
            if (NT == 2) { base = tile ? Bh : Ah; doff = tile ? TILE_B : 0u; }
            else {
                base = (tile == 0) ? Ah : (tile == 1) ? Al : Bh;
                doff = (uint32_t)tile * TILE_B;
            }
            cp16(sb + doff + r * 80 + s * 16, base + (size_t)r * HID + c * 32 + s * 8);
        }
    };

    cp_chunk(0, 0); CP_COMMIT();
    cp_chunk(1, 1); CP_COMMIT();
    cp_chunk(2, 2); CP_COMMIT();

    int buf = 0;
    for (int c = 0; c < NC; c++) {
        CP_WAIT2();
        __syncthreads();
        if (NPA == 2)
            chunk2(smb, buf * BUF, buf * BUF + TILE_B, buf * BUF + BOFF, lane, wm0, wn0, acc);
        else {
#pragma unroll
            for (int ks = 0; ks < 2; ks++) {
                const uint32_t rowsel = (uint32_t)(lane & 15) * 80
                                      + (uint32_t)((lane >> 4) + ks * 2) * 16;
                uint32_t aH[2][4], bH[4][4];
#pragma unroll
                for (int mt = 0; mt < 2; mt++)
                    ldm4(aH[mt], smb + buf * BUF + (uint32_t)(wm0 + mt * 16) * 80 + rowsel);
#pragma unroll
                for (int g = 0; g < 4; g++)
                    ldm4(bH[g], smb + buf * BUF + BOFF + (uint32_t)(wn0 + g * 16) * 80 + rowsel);
#pragma unroll
                for (int mt = 0; mt < 2; mt++)
#pragma unroll
                    for (int g = 0; g < 4; g++) {
                        mma16816(acc[mt][2 * g],     aH[mt], bH[g][0], bH[g][2]);
                        mma16816(acc[mt][2 * g + 1], aH[mt], bH[g][1], bH[g][3]);
                    }
            }
        }
        __syncthreads();
        if (c + 3 < NC) cp_chunk(buf, c + 3);
        CP_COMMIT();
        buf = (buf == 2) ? 0 : buf + 1;
    }

    // epilogue
    float* vec = (float*)(sm + 34048);
    if (MODE == 0) {
        if (t < 128) vec[t] = biasv[blockIdx.x * 128 + t];
    } else {
        if (t < 128) {
            vec[t]       = biasv[blockIdx.x * 128 + t] + g_Cc[t];
            vec[128 + t] = g_A0[t];
            vec[256 + t] = g_A1[t];
            vec[384 + t] = g_A2[t];
        }
        const int b = blockIdx.y >> 4, h = blockIdx.x;
        const int vpos0 = (blockIdx.y & 15) * 128;
        const float* lar = la + (size_t)(b * 8 + h) * VL;
        if (t < 130) {
            int g = vpos0 - 1 + t;
            vec[512 + t] = (g >= 0 && g < VL) ? lar[g] : 0.f;
        }
    }
    __syncthreads();

#pragma unroll
    for (int mt = 0; mt < 2; mt++) {
#pragma unroll
        for (int h2 = 0; h2 < 2; h2++) {
            const int row = wm0 + mt * 16 + (lane >> 2) + h2 * 8;
            size_t obase;
            float lm1 = 0.f, l0 = 0.f, lp1 = 0.f;
            if (MODE == 0) {
                obase = (((size_t)(blockIdx.x * 32 + blockIdx.y)) * QL + row) * 128;
            } else {
                int b = blockIdx.y >> 4, h = blockIdx.x;
                int vpos0 = (blockIdx.y & 15) * 128;
                lm1 = vec[512 + row]; l0 = vec[513 + row]; lp1 = vec[514 + row];
                obase = (((size_t)(h * 32 + b)) * VL + vpos0 + row) * 128;
            }
#pragma unroll
            for (int nt = 0; nt < 8; nt++) {
                const int col = wn0 + nt * 8 + 2 * (lane & 3);
                float x = acc[mt][nt][2 * h2];
                float y = acc[mt][nt][2 * h2 + 1];
                if (MODE == 0) {
                    x += vec[col]; y += vec[col + 1];
                    uint32_t lo, hi = sp2h(x, y, lo);
                    *(uint32_t*)&g_qh_h[obase + col] = hi;
                    *(uint32_t*)&g_qh_l[obase + col] = lo;
                } else {
                    x += vec[col]     + vec[128 + col]     * lm1 + vec[256 + col]     * l0 + vec[384 + col]     * lp1;
                    y += vec[col + 1] + vec[128 + col + 1] * lm1 + vec[256 + col + 1] * l0 + vec[384 + col + 1] * lp1;
                    uint32_t hi = pk2h(x, y);
                    *(uint32_t*)&g_vh_h[obase + col] = hi;
                    *(uint32_t*)(sm + (row * 65 + (col >> 1)) * 4) = hi;
                }
            }
        }
    }

    if (MODE == 1) {
        __syncthreads();
        const int b = blockIdx.y >> 4, h = blockIdx.x;
        const int vpos0 = (blockIdx.y & 15) * 128;
        const int d = t >> 1, vh2 = t & 1;
        size_t ob = (((size_t)(h * 32 + b)) * 128 + d) * VL + vpos0 + vh2 * 64;
#pragma unroll
        for (int blk = 0; blk < 8; blk++) {
            uint16_t e[8];
#pragma unroll
            for (int j = 0; j < 8; j++) {
                int v = vh2 * 64 + blk * 8 + j;
                e[j] = *(uint16_t*)(sm + (v * 65 + (d >> 1)) * 4 + (d & 1) * 2);
            }
            uint4 o;
            o.x = (uint32_t)e[0] | ((uint32_t)e[1] << 16);
            o.y = (uint32_t)e[2] | ((uint32_t)e[3] << 16);
            o.z = (uint32_t)e[4] | ((uint32_t)e[5] << 16);
            o.w = (uint32_t)e[6] | ((uint32_t)e[7] << 16);
            *(uint4*)&g_vhT_h[ob + blk * 8] = o;
        }
    }
}

// ---------------------------------------------------------------------------
// Fused attention: per (head,batch) item n: S = qh@vh^T/sqrt(D); two-pass
// online softmax; writes attn (fp32) and out = softmax(S)@vh.
// smem map (bytes):
//   QH[4]  @0       QL[4] @40960   Bbuf[2] @81920
//   PH[4]  @102400  PL[4] @143360  (PH area doubles as pass-1 4-ring)
//   redM @184320  redS @185344  m @186368  l @186880  linv @187392
// ---------------------------------------------------------------------------
static const int FUSED_SMEM = 187904;

__global__ void __launch_bounds__(256)
fused_attn(float* __restrict__ attn, float* __restrict__ outp)
{
    extern __shared__ char sm[];
    const uint32_t smb = smem_u32(sm);
    const int t = threadIdx.x, lane = t & 31, w = t >> 5;
    const int wm0 = (w & 3) * 32, wn0 = (w >> 2) * 64;
    const int n = blockIdx.x;

    const uint16_t* vhb = g_vh_h  + (size_t)n * VL * 128;
    const uint16_t* vtb = g_vhT_h + (size_t)n * 128 * VL;

    float* redM = (float*)(sm + 184320);
    float* redS = (float*)(sm + 185344);
    float* mrow = (float*)(sm + 186368);
    float* lrow = (float*)(sm + 186880);
    float* livr = (float*)(sm + 187392);

    if (t < 128) { mrow[t] = -1e30f; lrow[t] = 0.f; }

    // qh hi+lo -> smem (group 0)
    {
        const uint16_t* qh = g_qh_h + (size_t)n * 16384;
        const uint16_t* ql = g_qh_l + (size_t)n * 16384;
#pragma unroll
        for (int i = 0; i < 16; i++) {
            int idx = t + 256 * i;
            int prec = idx >> 11, rem = idx & 2047;
            int c = rem >> 9, r = (rem >> 2) & 127, s = rem & 3;
            cp16(smb + prec * 40960 + c * 10240 + r * 80 + s * 16,
                 (prec ? ql : qh) + r * 128 + c * 32 + s * 8);
        }
    }
    CP_COMMIT();

    auto cpB = [&](uint32_t dst, const uint16_t* base, int ld, int c) {
#pragma unroll
        for (int i = 0; i < 2; i++) {
            int idx = t + 256 * i;
            int r = (idx >> 2) & 127, s = idx & 3;
            cp16(smb + dst + r * 80 + s * 16, base + (size_t)r * ld + c * 32 + s * 8);
        }
    };

    const float scf = 0.08838834764831845f;   // 1/sqrt(128)
    float Sacc[2][8][4];

    // ------------------------------ pass 1 ------------------------------
#pragma unroll
    for (int j = 0; j < 4; j++) { cpB(102400u + j * 10240u, vhb, 128, j); CP_COMMIT(); }

    for (int g = 0; g < 64; g++) {
        const int c = g & 3;
        CP_WAIT3();
        __syncthreads();
        if (c == 0) {
#pragma unroll
            for (int i = 0; i < 2; i++)
#pragma unroll
                for (int j = 0; j < 8; j++)
#pragma unroll
                    for (int k = 0; k < 4; k++) Sacc[i][j][k] = 0.f;
        }
        chunk2(smb, c * 10240u, 40960u + c * 10240u, 102400u + (g & 3) * 10240u,
               lane, wm0, wn0, Sacc);
        __syncthreads();
        {
            int gn = g + 4;
            if (gn < 64) cpB(102400u + (gn & 3) * 10240u,
                             vhb + (size_t)(gn >> 2) * 16384, 128, gn & 3);
            CP_COMMIT();
        }
        if (c == 3) {
            // scale S in place
#pragma unroll
            for (int i = 0; i < 2; i++)
#pragma unroll
                for (int j = 0; j < 8; j++)
#pragma unroll
                    for (int k = 0; k < 4; k++) Sacc[i][j][k] *= scf;
            // row max -> redM halves
#pragma unroll
            for (int mt = 0; mt < 2; mt++)
#pragma unroll
                for (int h2 = 0; h2 < 2; h2++) {
                    float mx = -1e30f;
#pragma unroll
                    for (int nt = 0; nt < 8; nt++)
                        mx = fmaxf(mx, fmaxf(Sacc[mt][nt][2 * h2], Sacc[mt][nt][2 * h2 + 1]));
                    mx = fmaxf(mx, __shfl_xor_sync(~0u, mx, 1));
                    mx = fmaxf(mx, __shfl_xor_sync(~0u, mx, 2));
                    if ((lane & 3) == 0)
                        redM[(w >> 2) * 128 + wm0 + mt * 16 + (lane >> 2) + h2 * 8] = mx;
                }
            __syncthreads();
            if (w < 4 && (lane & 3) == 0) {
#pragma unroll
                for (int mt = 0; mt < 2; mt++)
#pragma unroll
                    for (int h2 = 0; h2 < 2; h2++) {
                        int row = wm0 + mt * 16 + (lane >> 2) + h2 * 8;
                        float tm = fmaxf(redM[row], redM[128 + row]);
                        float mo = mrow[row];
                        float mn = fmaxf(mo, tm);
                        lrow[row] *= __expf(mo - mn);
                        mrow[row] = mn;
                    }
            }
            __syncthreads();
            // row sum of exp -> redS halves
#pragma unroll
            for (int mt = 0; mt < 2; mt++)
#pragma unroll
                for (int h2 = 0; h2 < 2; h2++) {
                    int row = wm0 + mt * 16 + (lane >> 2) + h2 * 8;
                    float mm = mrow[row];
                    float s = 0.f;
#pragma unroll
                    for (int nt = 0; nt < 8; nt++)
                        s += __expf(Sacc[mt][nt][2 * h2] - mm)
                           + __expf(Sacc[mt][nt][2 * h2 + 1] - mm);
                    s += __shfl_xor_sync(~0u, s, 1);
                    s += __shfl_xor_sync(~0u, s, 2);
                    if ((lane & 3) == 0) redS[(w >> 2) * 128 + row] = s;
                }
            __syncthreads();
            if (w < 4 && (lane & 3) == 0) {
#pragma unroll
                for (int mt = 0; mt < 2; mt++)
#pragma unroll
                    for (int h2 = 0; h2 < 2; h2++) {
                        int row = wm0 + mt * 16 + (lane >> 2) + h2 * 8;
                        lrow[row] += redS[row] + redS[128 + row];
                    }
            }
            __syncthreads();
        }
    }
    if (t < 128) livr[t] = 1.0f / lrow[t];
    __syncthreads();

    // ------------------------------ pass 2 ------------------------------
    float Oacc[2][8][4];
#pragma unroll
    for (int i = 0; i < 2; i++)
#pragma unroll
        for (int j = 0; j < 8; j++)
#pragma unroll
            for (int k = 0; k < 4; k++) Oacc[i][j][k] = 0.f;

    cpB(81920u,          vhb, 128, 0); CP_COMMIT();
    cpB(81920u + 10240u, vhb, 128, 1); CP_COMMIT();

    for (int gg = 0; gg < 128; gg++) {
        const int vt = gg >> 3, ph = (gg >> 2) & 1, c = gg & 3;
        CP_WAIT1();
        __syncthreads();
        if (ph == 0) {
            if (c == 0) {
#pragma unroll
                for (int i = 0; i < 2; i++)
#pragma unroll
                    for (int j = 0; j < 8; j++)
#pragma unroll
                        for (int k = 0; k < 4; k++) Sacc[i][j][k] = 0.f;
            }
            chunk2(smb, c * 10240u, 40960u + c * 10240u, 81920u + (gg & 1) * 10240u,
                   lane, wm0, wn0, Sacc);
        } else {
            chunk2(smb, 102400u + c * 10240u, 143360u + c * 10240u,
                   81920u + (gg & 1) * 10240u, lane, wm0, wn0, Oacc);
        }
        __syncthreads();
        {
            int gn = gg + 2;
            if (gn < 128) {
                int vtn = gn >> 3, phn = (gn >> 2) & 1, cn = gn & 3;
                if (phn == 0) cpB(81920u + (gn & 1) * 10240u,
                                  vhb + (size_t)vtn * 16384, 128, cn);
                else          cpB(81920u + (gn & 1) * 10240u,
                                  vtb + (size_t)vtn * 128, VL, cn);
            }
            CP_COMMIT();
        }
        if (ph == 0 && c == 3) {
            // P = exp(S*scf - m) / l ; write attn; stage P hi/lo in smem
            float* adst0 = attn + (size_t)n * QL * VL + (size_t)vt * 128;
#pragma unroll
            for (int mt = 0; mt < 2; mt++)
#pragma unroll
                for (int h2 = 0; h2 < 2; h2++) {
                    int row = wm0 + mt * 16 + (lane >> 2) + h2 * 8;
                    float mm = mrow[row], li = livr[row];
                    float* ad = adst0 + (size_t)row * VL;
#pragma unroll
                    for (int nt = 0; nt < 8; nt++) {
                        int col = wn0 + nt * 8 + 2 * (lane & 3);
                        float s0 = Sacc[mt][nt][2 * h2] * scf;
                        float s1 = Sacc[mt][nt][2 * h2 + 1] * scf;
                        float p0 = __expf(s0 - mm) * li;
                        float p1 = __expf(s1 - mm) * li;
                        *(float2*)(ad + col) = make_float2(p0, p1);
                        uint32_t lo, hi = sp2h(p0, p1, lo);
                        uint32_t po = (uint32_t)(col >> 5) * 10240u + (uint32_t)row * 80u
                                    + (uint32_t)((col >> 3) & 3) * 16u + (uint32_t)(col & 7) * 2u;
                        *(uint32_t*)(sm + 102400 + po) = hi;
                        *(uint32_t*)(sm + 143360 + po) = lo;
                    }
                }
        }
    }

    // out epilogue
    const int h = n >> 5, b = n & 31;
#pragma unroll
    for (int mt = 0; mt < 2; mt++)
#pragma unroll
        for (int h2 = 0; h2 < 2; h2++) {
            int row = wm0 + mt * 16 + (lane >> 2) + h2 * 8;
            float* dst = outp + ((size_t)(b * QL + row)) * HID + h * 128;
#pragma unroll
            for (int nt = 0; nt < 8; nt++) {
                int col = wn0 + nt * 8 + 2 * (lane & 3);
                *(float2*)(dst + col) =
                    make_float2(Oacc[mt][nt][2 * h2], Oacc[mt][nt][2 * h2 + 1]);
            }
        }
}

// ---------------------------------------------------------------------------
DI void split_body(const float4* __restrict__ in, uint16_t* oh, uint16_t* ol, int n4) {
    int i = blockIdx.x * 256 + threadIdx.x;
    if (i >= n4) return;
    float4 x = in[i];
    uint32_t l0, l1;
    uint32_t h0 = sp2h(x.x, x.y, l0), h1 = sp2h(x.z, x.w, l1);
    uint2 H; H.x = h0; H.y = h1;
    *(uint2*)&oh[(size_t)i * 4] = H;
    if (ol) { uint2 L; L.x = l0; L.y = l1; *(uint2*)&ol[(size_t)i * 4] = L; }
}
__global__ void split_q_k(const float4* in)  { split_body(in, s_q_h, s_q_l, 1048576); }
__global__ void split_v_k(const float4* in)  { split_body(in, s_v_h, nullptr, 16777216); }
__global__ void split_wq_k(const float4* in) { split_body(in, s_Wq_h, nullptr, 262144); }
__global__ void split_wv_k(const float4* in) { split_body(in, s_Wv_h, nullptr, 262144); }

// ---------------------------------------------------------------------------
__global__ void prep_kernel(const float* __restrict__ conv_w,
                            const float* __restrict__ conv_b,
                            const float* __restrict__ Wloc)
{
    int d = threadIdx.x;
    float a0 = 0.f, a1 = 0.f, a2 = 0.f, c = 0.f;
#pragma unroll
    for (int cc = 0; cc < 10; cc++) {
        float wl = Wloc[d * 10 + cc];
        a0 += wl * conv_w[cc * 3 + 0];
        a1 += wl * conv_w[cc * 3 + 1];
        a2 += wl * conv_w[cc * 3 + 2];
        c  += wl * conv_b[cc];
    }
    g_A0[d] = a0; g_A1[d] = a1; g_A2[d] = a2; g_Cc[d] = c;
}

// ---------------------------------------------------------------------------
extern "C" void kernel_launch(void* const* d_in, const int* in_sizes, int n_in,
                              void* d_out, int out_size)
{
    const float* q         = (const float*)d_in[0];
    const float* v         = (const float*)d_in[1];
    const float* last_attn = (const float*)d_in[2];
    const float* conv_w    = (const float*)d_in[3];
    const float* conv_b    = (const float*)d_in[4];
    const float* Wq        = (const float*)d_in[5];
    const float* bq        = (const float*)d_in[6];
    const float* Wv        = (const float*)d_in[7];
    const float* Wloc      = (const float*)d_in[8];
    const float* bias      = (const float*)d_in[9];

    float* out  = (float*)d_out;
    float* attn = out + 4194304;

    const int SM3 = 3 * 3 * TILE_B;   // 92160 (mode 0)
    const int SM2 = 3 * 2 * TILE_B;   // 61440 (mode 1)

    static bool attr_done = false;
    if (!attr_done) {
        cudaFuncSetAttribute(mma_gemm<0>, cudaFuncAttributeMaxDynamicSharedMemorySize, SM3);
        cudaFuncSetAttribute(mma_gemm<1>, cudaFuncAttributeMaxDynamicSharedMemorySize, SM2);
        cudaFuncSetAttribute(fused_attn, cudaFuncAttributeMaxDynamicSharedMemorySize, FUSED_SMEM);
        attr_done = true;
    }

    prep_kernel<<<1, 128>>>(conv_w, conv_b, Wloc);
    split_q_k <<<4096,  256>>>((const float4*)q);
    split_v_k <<<65536, 256>>>((const float4*)v);
    split_wq_k<<<1024,  256>>>((const float4*)Wq);
    split_wv_k<<<1024,  256>>>((const float4*)Wv);

    mma_gemm<0><<<dim3(8, 32),  256, SM3>>>(bq,   nullptr);
    mma_gemm<1><<<dim3(8, 512), 256, SM2>>>(bias, last_attn);
    fused_attn<<<256, 256, FUSED_SMEM>>>(attn, out);
}

// round 7
// speedup vs baseline: 1.0010x; 1.0010x over previous
#include <cuda_runtime.h>
#include <cuda_fp16.h>
#include <cstdint>

#define DI __device__ __forceinline__

static const int QL  = 128;
static const int VL  = 2048;
static const int HID = 1024;

// ---------------------------------------------------------------------------
// Scratch (device globals; no runtime allocation allowed). fp16 operands.
// ---------------------------------------------------------------------------
__device__ uint16_t s_q_h[4194304],  s_q_l[4194304];    // split q
__device__ uint16_t s_v_h[67108864];                    // v hi only (1-pass A)
__device__ uint16_t s_Wq_h[1048576];                    // Wq hi (B-side only)
__device__ uint16_t s_Wv_h[1048576];                    // Wv hi
__device__ uint16_t g_qh_h[4194304], g_qh_l[4194304];   // qp result [n][q][d]
__device__ uint16_t g_vh_h[67108864];                   // vp result [n][v][d]
__device__ uint16_t g_vhT_h[67108864];                  // vp result [n][d][v]
__device__ float g_A0[128], g_A1[128], g_A2[128], g_Cc[128];

// ---------------------------------------------------------------------------
DI uint32_t smem_u32(const void* p) {
    uint32_t a;
    asm("{ .reg .u64 t; cvta.to.shared.u64 t, %1; cvt.u32.u64 %0, t; }" : "=r"(a) : "l"(p));
    return a;
}

DI uint32_t sp2h(float a, float b, uint32_t& lo) {
    __half2 h = __floats2half2_rn(a, b);
    float2 f = __half22float2(h);
    __half2 l = __floats2half2_rn(a - f.x, b - f.y);
    lo = *(uint32_t*)&l;
    return *(uint32_t*)&h;
}
DI uint32_t pk2h(float a, float b) {
    __half2 h = __floats2half2_rn(a, b);
    return *(uint32_t*)&h;
}

DI void ldm4(uint32_t* r, uint32_t a) {
    asm volatile("ldmatrix.sync.aligned.m8n8.x4.shared.b16 {%0,%1,%2,%3}, [%4];"
        : "=r"(r[0]), "=r"(r[1]), "=r"(r[2]), "=r"(r[3]) : "r"(a));
}

DI void mma16816(float* d, const uint32_t* a, uint32_t b0, uint32_t b1) {
    asm volatile("mma.sync.aligned.m16n8k16.row.col.f32.f16.f16.f32 "
        "{%0,%1,%2,%3},{%4,%5,%6,%7},{%8,%9},{%0,%1,%2,%3};"
        : "+f"(d[0]), "+f"(d[1]), "+f"(d[2]), "+f"(d[3])
        : "r"(a[0]), "r"(a[1]), "r"(a[2]), "r"(a[3]), "r"(b0), "r"(b1));
}

DI void cp16(uint32_t dst, const void* src) {
    asm volatile("cp.async.cg.shared.global [%0], [%1], 16;" :: "r"(dst), "l"(src));
}
#define CP_COMMIT() asm volatile("cp.async.commit_group;" ::: "memory")
#define CP_WAIT2()  asm volatile("cp.async.wait_group 2;"  ::: "memory")
#define CP_WAIT0()  asm volatile("cp.async.wait_group 0;"  ::: "memory")

static const int TILE_B = 10240;

// 2-pass mma on one 32-K chunk, 128x128 tile (projection GEMMs)
DI void chunk2(uint32_t smb, uint32_t aH0, uint32_t aL0, uint32_t b0,
               int lane, int wm0, int wn0, float (&acc)[2][8][4]) {
#pragma unroll
    for (int ks = 0; ks < 2; ks++) {
        const uint32_t rowsel = (uint32_t)(lane & 15) * 80
                              + (uint32_t)((lane >> 4) + ks * 2) * 16;
        uint32_t aH[2][4], aL[2][4], bH[4][4];
#pragma unroll
        for (int mt = 0; mt < 2; mt++) {
            ldm4(aH[mt], smb + aH0 + (uint32_t)(wm0 + mt * 16) * 80 + rowsel);
            ldm4(aL[mt], smb + aL0 + (uint32_t)(wm0 + mt * 16) * 80 + rowsel);
        }
#pragma unroll
        for (int g = 0; g < 4; g++)
            ldm4(bH[g], smb + b0 + (uint32_t)(wn0 + g * 16) * 80 + rowsel);
#pragma unroll
        for (int mt = 0; mt < 2; mt++)
#pragma unroll
            for (int g = 0; g < 4; g++) {
                mma16816(acc[mt][2 * g],     aH[mt], bH[g][0], bH[g][2]);
                mma16816(acc[mt][2 * g + 1], aH[mt], bH[g][1], bH[g][3]);
            }
#pragma unroll
        for (int mt = 0; mt < 2; mt++)
#pragma unroll
            for (int g = 0; g < 4; g++) {
                mma16816(acc[mt][2 * g],     aL[mt], bH[g][0], bH[g][2]);
                mma16816(acc[mt][2 * g + 1], aL[mt], bH[g][1], bH[g][3]);
            }
    }
}

// ---------------------------------------------------------------------------
// Projection GEMMs (unchanged from round 5)
// MODE 0: qp = q@Wq^T + bq          -> g_qh_h/l        grid(8, 32)
// MODE 1: vp = v@Wv^T + bias + loc  -> g_vh_h, g_vhT_h grid(8, 512)  (A 1-pass)
// ---------------------------------------------------------------------------
template <int MODE>
__global__ void __launch_bounds__(256)
mma_gemm(const float* __restrict__ biasv, const float* __restrict__ la)
{
    extern __shared__ char sm[];
    const uint32_t smb = smem_u32(sm);
    const int t = threadIdx.x, lane = t & 31, w = t >> 5;
    const int wm0 = (w & 3) * 32, wn0 = (w >> 2) * 64;

    constexpr int NC  = HID / 32;
    constexpr int NPA = (MODE == 1) ? 1 : 2;
    constexpr int NT  = (MODE == 1) ? 2 : 3;
    constexpr int BUF = NT * TILE_B;
    constexpr uint32_t BOFF = (uint32_t)(NT - 1) * TILE_B;

    const uint16_t *Ah, *Al = nullptr, *Bh;
    if (MODE == 0) {
        size_t ao = (size_t)blockIdx.y * 128 * HID, bo = (size_t)blockIdx.x * 128 * HID;
        Ah = s_q_h + ao; Al = s_q_l + ao; Bh = s_Wq_h + bo;
    } else {
        size_t ao = (size_t)blockIdx.y * 128 * HID, bo = (size_t)blockIdx.x * 128 * HID;
        Ah = s_v_h + ao; Bh = s_Wv_h + bo;
    }

    float acc[2][8][4];
#pragma unroll
    for (int i = 0; i < 2; i++)
#pragma unroll
        for (int j = 0; j < 8; j++)
#pragma unroll
            for (int k = 0; k < 4; k++) acc[i][j][k] = 0.f;

    auto cp_chunk = [&](int buf, int c) {
        uint32_t sb = smb + buf * BUF;
#pragma unroll
        for (int i = 0; i < NT * 2; i++) {
            int idx = t + 256 * i;
            int tile = idx >> 9, r = (idx >> 2) & 127, s = idx & 3;
            const uint16_t* base; uint32_t doff;
            if (NT == 2) { base = tile ? Bh : Ah; doff = tile ? TILE_B : 0u; }
            else {
                base = (tile == 0) ? Ah : (tile == 1) ? Al : Bh;
                doff = (uint32_t)tile * TILE_B;
            }
            cp16(sb + doff + r * 80 + s * 16, base + (size_t)r * HID + c * 32 + s * 8);
        }
    };

    cp_chunk(0, 0); CP_COMMIT();
    cp_chunk(1, 1); CP_COMMIT();
    cp_chunk(2, 2); CP_COMMIT();

    int buf = 0;
    for (int c = 0; c < NC; c++) {
        CP_WAIT2();
        __syncthreads();
        if (NPA == 2)
            chunk2(smb, buf * BUF, buf * BUF + TILE_B, buf * BUF + BOFF, lane, wm0, wn0, acc);
        else {
#pragma unroll
            for (int ks = 0; ks < 2; ks++) {
                const uint32_t rowsel = (uint32_t)(lane & 15) * 80
                                      + (uint32_t)((lane >> 4) + ks * 2) * 16;
                uint32_t aH[2][4], bH[4][4];
#pragma unroll
                for (int mt = 0; mt < 2; mt++)
                    ldm4(aH[mt], smb + buf * BUF + (uint32_t)(wm0 + mt * 16) * 80 + rowsel);
#pragma unroll
                for (int g = 0; g < 4; g++)
                    ldm4(bH[g], smb + buf * BUF + BOFF + (uint32_t)(wn0 + g * 16) * 80 + rowsel);
#pragma unroll
                for (int mt = 0; mt < 2; mt++)
#pragma unroll
                    for (int g = 0; g < 4; g++) {
                        mma16816(acc[mt][2 * g],     aH[mt], bH[g][0], bH[g][2]);
                        mma16816(acc[mt][2 * g + 1], aH[mt], bH[g][1], bH[g][3]);
                    }
            }
        }
        __syncthreads();
        if (c + 3 < NC) cp_chunk(buf, c + 3);
        CP_COMMIT();
        buf = (buf == 2) ? 0 : buf + 1;
    }

    // epilogue
    float* vec = (float*)(sm + 34048);
    if (MODE == 0) {
        if (t < 128) vec[t] = biasv[blockIdx.x * 128 + t];
    } else {
        if (t < 128) {
            vec[t]       = biasv[blockIdx.x * 128 + t] + g_Cc[t];
            vec[128 + t] = g_A0[t];
            vec[256 + t] = g_A1[t];
            vec[384 + t] = g_A2[t];
        }
        const int b = blockIdx.y >> 4, h = blockIdx.x;
        const int vpos0 = (blockIdx.y & 15) * 128;
        const float* lar = la + (size_t)(b * 8 + h) * VL;
        if (t < 130) {
            int g = vpos0 - 1 + t;
            vec[512 + t] = (g >= 0 && g < VL) ? lar[g] : 0.f;
        }
    }
    __syncthreads();

#pragma unroll
    for (int mt = 0; mt < 2; mt++) {
#pragma unroll
        for (int h2 = 0; h2 < 2; h2++) {
            const int row = wm0 + mt * 16 + (lane >> 2) + h2 * 8;
            size_t obase;
            float lm1 = 0.f, l0 = 0.f, lp1 = 0.f;
            if (MODE == 0) {
                obase = (((size_t)(blockIdx.x * 32 + blockIdx.y)) * QL + row) * 128;
            } else {
                int b = blockIdx.y >> 4, h = blockIdx.x;
                int vpos0 = (blockIdx.y & 15) * 128;
                lm1 = vec[512 + row]; l0 = vec[513 + row]; lp1 = vec[514 + row];
                obase = (((size_t)(h * 32 + b)) * VL + vpos0 + row) * 128;
            }
#pragma unroll
            for (int nt = 0; nt < 8; nt++) {
                const int col = wn0 + nt * 8 + 2 * (lane & 3);
                float x = acc[mt][nt][2 * h2];
                float y = acc[mt][nt][2 * h2 + 1];
                if (MODE == 0) {
                    x += vec[col]; y += vec[col + 1];
                    uint32_t lo, hi = sp2h(x, y, lo);
                    *(uint32_t*)&g_qh_h[obase + col] = hi;
                    *(uint32_t*)&g_qh_l[obase + col] = lo;
                } else {
                    x += vec[col]     + vec[128 + col]     * lm1 + vec[256 + col]     * l0 + vec[384 + col]     * lp1;
                    y += vec[col + 1] + vec[128 + col + 1] * lm1 + vec[256 + col + 1] * l0 + vec[384 + col + 1] * lp1;
                    uint32_t hi = pk2h(x, y);
                    *(uint32_t*)&g_vh_h[obase + col] = hi;
                    *(uint32_t*)(sm + (row * 65 + (col >> 1)) * 4) = hi;
                }
            }
        }
    }

    if (MODE == 1) {
        __syncthreads();
        const int b = blockIdx.y >> 4, h = blockIdx.x;
        const int vpos0 = (blockIdx.y & 15) * 128;
        const int d = t >> 1, vh2 = t & 1;
        size_t ob = (((size_t)(h * 32 + b)) * 128 + d) * VL + vpos0 + vh2 * 64;
#pragma unroll
        for (int blk = 0; blk < 8; blk++) {
            uint16_t e[8];
#pragma unroll
            for (int j = 0; j < 8; j++) {
                int v = vh2 * 64 + blk * 8 + j;
                e[j] = *(uint16_t*)(sm + (v * 65 + (d >> 1)) * 4 + (d & 1) * 2);
            }
            uint4 o;
            o.x = (uint32_t)e[0] | ((uint32_t)e[1] << 16);
            o.y = (uint32_t)e[2] | ((uint32_t)e[3] << 16);
            o.z = (uint32_t)e[4] | ((uint32_t)e[5] << 16);
            o.w = (uint32_t)e[6] | ((uint32_t)e[7] << 16);
            *(uint4*)&g_vhT_h[ob + blk * 8] = o;
        }
    }
}

// ---------------------------------------------------------------------------
// Fused attention v2: grid (256 n, 2 qsplit), 64 q-rows per CTA, 2 CTAs/SM.
// Per-thread online softmax stats (no in-loop block reductions).
// smem (bytes): QH@0 QL@20480 PH@40960 PL@61440 BRING(3x10240)@81920
//               stats(mrow/livr)@112640 ; total 113152
// ---------------------------------------------------------------------------
static const int F_QH = 0, F_QL = 20480, F_PH = 40960, F_PL = 61440;
static const int F_BR = 81920, F_ST = 112640;
static const int FUSED_SMEM = 113152;
static const int PCH = 5120;   // 64 rows x 80B per 32-k chunk

// 64-row-tile chunk: A[64x32] (hi/lo), B[128x32]; warp layout 2m x 4n (32x32)
template <bool TWOPASS>
DI void chunk64(uint32_t smb, uint32_t aH0, uint32_t aL0, uint32_t b0,
                int lane, int wm0, int wn0, float (&acc)[2][4][4]) {
#pragma unroll
    for (int ks = 0; ks < 2; ks++) {
        const uint32_t rowsel = (uint32_t)(lane & 15) * 80
                              + (uint32_t)((lane >> 4) + ks * 2) * 16;
        uint32_t aH[2][4], aL[2][4], bH[2][4];
#pragma unroll
        for (int mt = 0; mt < 2; mt++) {
            ldm4(aH[mt], smb + aH0 + (uint32_t)(wm0 + mt * 16) * 80 + rowsel);
            if (TWOPASS) ldm4(aL[mt], smb + aL0 + (uint32_t)(wm0 + mt * 16) * 80 + rowsel);
        }
#pragma unroll
        for (int g = 0; g < 2; g++)
            ldm4(bH[g], smb + b0 + (uint32_t)(wn0 + g * 16) * 80 + rowsel);
#pragma unroll
        for (int mt = 0; mt < 2; mt++)
#pragma unroll
            for (int g = 0; g < 2; g++) {
                mma16816(acc[mt][2 * g],     aH[mt], bH[g][0], bH[g][2]);
                mma16816(acc[mt][2 * g + 1], aH[mt], bH[g][1], bH[g][3]);
            }
        if (TWOPASS) {
#pragma unroll
            for (int mt = 0; mt < 2; mt++)
#pragma unroll
                for (int g = 0; g < 2; g++) {
                    mma16816(acc[mt][2 * g],     aL[mt], bH[g][0], bH[g][2]);
                    mma16816(acc[mt][2 * g + 1], aL[mt], bH[g][1], bH[g][3]);
                }
        }
    }
}

__global__ void __launch_bounds__(256, 2)
fused_attn(float* __restrict__ attn, float* __restrict__ outp)
{
    extern __shared__ char sm[];
    const uint32_t smb = smem_u32(sm);
    const int t = threadIdx.x, lane = t & 31, w = t >> 5;
    const int wm0 = (w & 1) * 32, wn0 = (w >> 1) * 32;
    const int n = blockIdx.x, q0 = blockIdx.y * 64;

    const uint16_t* vhb = g_vh_h  + (size_t)n * VL * 128;
    const uint16_t* vtb = g_vhT_h + (size_t)n * 128 * VL;

    float* mrow = (float*)(sm + F_ST);        // [64]
    float* livr = mrow + 64;                  // [64]

    // --- load qh hi+lo (64 rows) ---
    {
        const uint16_t* qh = g_qh_h + (size_t)n * 16384 + (size_t)q0 * 128;
        const uint16_t* ql = g_qh_l + (size_t)n * 16384 + (size_t)q0 * 128;
#pragma unroll
        for (int i = 0; i < 8; i++) {
            int idx = t + 256 * i;
            int prec = idx >> 10, rem = idx & 1023;
            int c = rem >> 8, r = (rem >> 2) & 63, s = rem & 3;
            cp16(smb + prec * 20480 + c * PCH + r * 80 + s * 16,
                 (prec ? ql : qh) + r * 128 + c * 32 + s * 8);
        }
    }

    // B-tile loader: 128 rows x 32 cols
    auto cpB = [&](int slot, const uint16_t* base, int ld, int c) {
        uint32_t sb = smb + F_BR + slot * TILE_B;
#pragma unroll
        for (int i = 0; i < 2; i++) {
            int idx = t + 256 * i;
            int r = (idx >> 2) & 127, s = idx & 3;
            cp16(sb + r * 80 + s * 16, base + (size_t)r * ld + c * 32 + s * 8);
        }
    };

    const float scf = 0.08838834764831845f;   // 1/sqrt(128)
    float Sacc[2][4][4];
    float m_r[4], l_r[4];
#pragma unroll
    for (int i = 0; i < 4; i++) { m_r[i] = -1e30f; l_r[i] = 0.f; }

    // =========================== pass 1 ===========================
    cpB(0, vhb, 128, 0); CP_COMMIT();   // group includes QH/QL above
    cpB(1, vhb, 128, 1); CP_COMMIT();
    cpB(2, vhb, 128, 2); CP_COMMIT();

    for (int g = 0; g < 64; g++) {
        const int c = g & 3, slot = g % 3;
        CP_WAIT2();
        __syncthreads();
        if (c == 0) {
#pragma unroll
            for (int i = 0; i < 2; i++)
#pragma unroll
                for (int j = 0; j < 4; j++)
#pragma unroll
                    for (int k = 0; k < 4; k++) Sacc[i][j][k] = 0.f;
        }
        chunk64<true>(smb, F_QH + c * PCH, F_QL + c * PCH,
                      F_BR + slot * TILE_B, lane, wm0, wn0, Sacc);
        __syncthreads();
        {
            int gn = g + 3;
            if (gn < 64) cpB(gn % 3, vhb + (size_t)(gn >> 2) * 16384, 128, gn & 3);
            CP_COMMIT();
        }
        if (c == 3) {
            // per-thread online stats over this thread's 8 cols x 4 rows
#pragma unroll
            for (int mt = 0; mt < 2; mt++)
#pragma unroll
                for (int h2 = 0; h2 < 2; h2++) {
                    const int r4 = mt * 2 + h2;
                    float mx = -1e30f;
#pragma unroll
                    for (int nt = 0; nt < 4; nt++)
                        mx = fmaxf(mx, fmaxf(Sacc[mt][nt][2 * h2], Sacc[mt][nt][2 * h2 + 1]));
                    mx *= scf;
                    float mn = fmaxf(m_r[r4], mx);
                    float s = 0.f;
#pragma unroll
                    for (int nt = 0; nt < 4; nt++)
                        s += __expf(Sacc[mt][nt][2 * h2] * scf - mn)
                           + __expf(Sacc[mt][nt][2 * h2 + 1] * scf - mn);
                    l_r[r4] = l_r[r4] * __expf(m_r[r4] - mn) + s;
                    m_r[r4] = mn;
                }
        }
    }
    CP_WAIT0();
    __syncthreads();

    // merge stats: quad (lane xor 1,2), then across 4 n-warps via smem
#pragma unroll
    for (int r4 = 0; r4 < 4; r4++) {
#pragma unroll
        for (int sh = 1; sh <= 2; sh <<= 1) {
            float mo = __shfl_xor_sync(~0u, m_r[r4], sh);
            float lo = __shfl_xor_sync(~0u, l_r[r4], sh);
            float mn = fmaxf(m_r[r4], mo);
            l_r[r4] = l_r[r4] * __expf(m_r[r4] - mn) + lo * __expf(mo - mn);
            m_r[r4] = mn;
        }
    }
    {
        float* mred = (float*)(sm + F_PH);          // [4][64]
        float* lred = mred + 256;                   // [4][64]
        if ((lane & 3) == 0) {
            const int ng = w >> 1;
#pragma unroll
            for (int mt = 0; mt < 2; mt++)
#pragma unroll
                for (int h2 = 0; h2 < 2; h2++) {
                    int row = wm0 + mt * 16 + (lane >> 2) + h2 * 8;
                    mred[ng * 64 + row] = m_r[mt * 2 + h2];
                    lred[ng * 64 + row] = l_r[mt * 2 + h2];
                }
        }
        __syncthreads();
        if (t < 64) {
            float m = fmaxf(fmaxf(mred[t], mred[64 + t]), fmaxf(mred[128 + t], mred[192 + t]));
            float l = lred[t] * __expf(mred[t] - m) + lred[64 + t] * __expf(mred[64 + t] - m)
                    + lred[128 + t] * __expf(mred[128 + t] - m) + lred[192 + t] * __expf(mred[192 + t] - m);
            mrow[t] = m;
            livr[t] = 1.0f / l;
        }
        __syncthreads();
    }

    // =========================== pass 2 ===========================
    // gg: vt = gg>>3, phase = (gg>>2)&1 (0=S recompute, 1=O acc), c = gg&3
    float Oacc[2][4][4];
#pragma unroll
    for (int i = 0; i < 2; i++)
#pragma unroll
        for (int j = 0; j < 4; j++)
#pragma unroll
            for (int k = 0; k < 4; k++) Oacc[i][j][k] = 0.f;

    auto cpB2 = [&](int gg) {
        int vt = gg >> 3, ph = (gg >> 2) & 1, c = gg & 3, slot = gg % 3;
        if (ph == 0) cpB(slot, vhb + (size_t)vt * 16384, 128, c);
        else         cpB(slot, vtb + (size_t)vt * 128, VL, c);
    };
    cpB2(0); CP_COMMIT();
    cpB2(1); CP_COMMIT();
    cpB2(2); CP_COMMIT();

    for (int gg = 0; gg < 128; gg++) {
        const int vt = gg >> 3, ph = (gg >> 2) & 1, c = gg & 3, slot = gg % 3;
        CP_WAIT2();
        __syncthreads();
        if (ph == 0) {
            if (c == 0) {
#pragma unroll
                for (int i = 0; i < 2; i++)
#pragma unroll
                    for (int j = 0; j < 4; j++)
#pragma unroll
                        for (int k = 0; k < 4; k++) Sacc[i][j][k] = 0.f;
            }
            chunk64<true>(smb, F_QH + c * PCH, F_QL + c * PCH,
                          F_BR + slot * TILE_B, lane, wm0, wn0, Sacc);
        } else {
            chunk64<true>(smb, F_PH + c * PCH, F_PL + c * PCH,
                          F_BR + slot * TILE_B, lane, wm0, wn0, Oacc);
        }
        __syncthreads();
        {
            int gn = gg + 3;
            if (gn < 128) cpB2(gn);
            CP_COMMIT();
        }
        if (ph == 0 && c == 3) {
            // P = exp(S*scf - m) * linv ; write attn ; stage P hi/lo in smem
            float* adst0 = attn + (size_t)n * QL * VL + (size_t)(q0) * VL + (size_t)vt * 128;
#pragma unroll
            for (int mt = 0; mt < 2; mt++)
#pragma unroll
                for (int h2 = 0; h2 < 2; h2++) {
                    int row = wm0 + mt * 16 + (lane >> 2) + h2 * 8;
                    float mm = mrow[row], li = livr[row];
                    float* ad = adst0 + (size_t)row * VL;
#pragma unroll
                    for (int nt = 0; nt < 4; nt++) {
                        int col = wn0 + nt * 8 + 2 * (lane & 3);
                        float p0 = __expf(Sacc[mt][nt][2 * h2]     * scf - mm) * li;
                        float p1 = __expf(Sacc[mt][nt][2 * h2 + 1] * scf - mm) * li;
                        *(float2*)(ad + col) = make_float2(p0, p1);
                        uint32_t lo, hi = sp2h(p0, p1, lo);
                        uint32_t po = (uint32_t)(col >> 5) * PCH + (uint32_t)row * 80u
                                    + (uint32_t)((col >> 3) & 3) * 16u + (uint32_t)(col & 7) * 2u;
                        *(uint32_t*)(sm + F_PH + po) = hi;
                        *(uint32_t*)(sm + F_PL + po) = lo;
                    }
                }
        }
    }

    // out epilogue
    const int h = n >> 5, b = n & 31;
#pragma unroll
    for (int mt = 0; mt < 2; mt++)
#pragma unroll
        for (int h2 = 0; h2 < 2; h2++) {
            int row = q0 + wm0 + mt * 16 + (lane >> 2) + h2 * 8;
            float* dst = outp + ((size_t)(b * QL + row)) * HID + h * 128;
#pragma unroll
            for (int nt = 0; nt < 4; nt++) {
                int col = wn0 + nt * 8 + 2 * (lane & 3);
                *(float2*)(dst + col) =
                    make_float2(Oacc[mt][nt][2 * h2], Oacc[mt][nt][2 * h2 + 1]);
            }
        }
}

// ---------------------------------------------------------------------------
DI void split_body(const float4* __restrict__ in, uint16_t* oh, uint16_t* ol, int n4) {
    int i = blockIdx.x * 256 + threadIdx.x;
    if (i >= n4) return;
    float4 x = in[i];
    uint32_t l0, l1;
    uint32_t h0 = sp2h(x.x, x.y, l0), h1 = sp2h(x.z, x.w, l1);
    uint2 H; H.x = h0; H.y = h1;
    *(uint2*)&oh[(size_t)i * 4] = H;
    if (ol) { uint2 L; L.x = l0; L.y = l1; *(uint2*)&ol[(size_t)i * 4] = L; }
}
__global__ void split_q_k(const float4* in)  { split_body(in, s_q_h, s_q_l, 1048576); }
__global__ void split_v_k(const float4* in)  { split_body(in, s_v_h, nullptr, 16777216); }
__global__ void split_wq_k(const float4* in) { split_body(in, s_Wq_h, nullptr, 262144); }
__global__ void split_wv_k(const float4* in) { split_body(in, s_Wv_h, nullptr, 262144); }

// ---------------------------------------------------------------------------
__global__ void prep_kernel(const float* __restrict__ conv_w,
                            const float* __restrict__ conv_b,
                            const float* __restrict__ Wloc)
{
    int d = threadIdx.x;
    float a0 = 0.f, a1 = 0.f, a2 = 0.f, c = 0.f;
#pragma unroll
    for (int cc = 0; cc < 10; cc++) {
        float wl = Wloc[d * 10 + cc];
        a0 += wl * conv_w[cc * 3 + 0];
        a1 += wl * conv_w[cc * 3 + 1];
        a2 += wl * conv_w[cc * 3 + 2];
        c  += wl * conv_b[cc];
    }
    g_A0[d] = a0; g_A1[d] = a1; g_A2[d] = a2; g_Cc[d] = c;
}

// ---------------------------------------------------------------------------
extern "C" void kernel_launch(void* const* d_in, const int* in_sizes, int n_in,
                              void* d_out, int out_size)
{
    const float* q         = (const float*)d_in[0];
    const float* v         = (const float*)d_in[1];
    const float* last_attn = (const float*)d_in[2];
    const float* conv_w    = (const float*)d_in[3];
    const float* conv_b    = (const float*)d_in[4];
    const float* Wq        = (const float*)d_in[5];
    const float* bq        = (const float*)d_in[6];
    const float* Wv        = (const float*)d_in[7];
    const float* Wloc      = (const float*)d_in[8];
    const float* bias      = (const float*)d_in[9];

    float* out  = (float*)d_out;
    float* attn = out + 4194304;

    const int SM3 = 3 * 3 * TILE_B;   // 92160 (mode 0)
    const int SM2 = 3 * 2 * TILE_B;   // 61440 (mode 1)

    static bool attr_done = false;
    if (!attr_done) {
        cudaFuncSetAttribute(mma_gemm<0>, cudaFuncAttributeMaxDynamicSharedMemorySize, SM3);
        cudaFuncSetAttribute(mma_gemm<1>, cudaFuncAttributeMaxDynamicSharedMemorySize, SM2);
        cudaFuncSetAttribute(fused_attn, cudaFuncAttributeMaxDynamicSharedMemorySize, FUSED_SMEM);
        attr_done = true;
    }

    prep_kernel<<<1, 128>>>(conv_w, conv_b, Wloc);
    split_q_k <<<4096,  256>>>((const float4*)q);
    split_v_k <<<65536, 256>>>((const float4*)v);
    split_wq_k<<<1024,  256>>>((const float4*)Wq);
    split_wv_k<<<1024,  256>>>((const float4*)Wv);

    mma_gemm<0><<<dim3(8, 32),  256, SM3>>>(bq,   nullptr);
    mma_gemm<1><<<dim3(8, 512), 256, SM2>>>(bias, last_attn);
    fused_attn<<<dim3(256, 2), 256, FUSED_SMEM>>>(attn, out);
}

// round 8
// speedup vs baseline: 1.1278x; 1.1267x over previous
#include <cuda_runtime.h>
#include <cuda_fp16.h>
#include <cstdint>

#define DI __device__ __forceinline__

static const int QL  = 128;
static const int VL  = 2048;
static const int HID = 1024;

// ---------------------------------------------------------------------------
// Scratch (device globals; no runtime allocation allowed). fp16 operands.
// ---------------------------------------------------------------------------
__device__ uint16_t s_q_h[4194304],  s_q_l[4194304];    // split q
__device__ uint16_t s_v_h[67108864];                    // v hi only (1-pass A)
__device__ uint16_t s_Wq_h[1048576];                    // Wq hi (B-side only)
__device__ uint16_t s_Wv_h[1048576];                    // Wv hi
__device__ uint16_t g_qh_h[4194304], g_qh_l[4194304];   // qp result [n][q][d]
__device__ uint16_t g_vh_h[67108864];                   // vp result [n][v][d]
__device__ uint16_t g_vhT_h[67108864];                  // vp result [n][d][v]
__device__ float g_A0[128], g_A1[128], g_A2[128], g_Cc[128];

// ---------------------------------------------------------------------------
DI uint32_t smem_u32(const void* p) {
    uint32_t a;
    asm("{ .reg .u64 t; cvta.to.shared.u64 t, %1; cvt.u32.u64 %0, t; }" : "=r"(a) : "l"(p));
    return a;
}

DI uint32_t sp2h(float a, float b, uint32_t& lo) {
    __half2 h = __floats2half2_rn(a, b);
    float2 f = __half22float2(h);
    __half2 l = __floats2half2_rn(a - f.x, b - f.y);
    lo = *(uint32_t*)&l;
    return *(uint32_t*)&h;
}
DI uint32_t pk2h(float a, float b) {
    __half2 h = __floats2half2_rn(a, b);
    return *(uint32_t*)&h;
}

DI void ldm4(uint32_t* r, uint32_t a) {
    asm volatile("ldmatrix.sync.aligned.m8n8.x4.shared.b16 {%0,%1,%2,%3}, [%4];"
        : "=r"(r[0]), "=r"(r[1]), "=r"(r[2]), "=r"(r[3]) : "r"(a));
}

DI void mma16816(float* d, const uint32_t* a, uint32_t b0, uint32_t b1) {
    asm volatile("mma.sync.aligned.m16n8k16.row.col.f32.f16.f16.f32 "
        "{%0,%1,%2,%3},{%4,%5,%6,%7},{%8,%9},{%0,%1,%2,%3};"
        : "+f"(d[0]), "+f"(d[1]), "+f"(d[2]), "+f"(d[3])
        : "r"(a[0]), "r"(a[1]), "r"(a[2]), "r"(a[3]), "r"(b0), "r"(b1));
}

DI void cp16(uint32_t dst, const void* src) {
    asm volatile("cp.async.cg.shared.global [%0], [%1], 16;" :: "r"(dst), "l"(src));
}
#define CP_COMMIT() asm volatile("cp.async.commit_group;" ::: "memory")
#define CP_WAIT2()  asm volatile("cp.async.wait_group 2;"  ::: "memory")

static const int TILE_B = 10240;

// ---------------------------------------------------------------------------
// Unified GEMM, 128x128 tile, 3-stage cp.async pipeline, 2 CTAs/SM.
// MODE 0: qp = q@Wq^T + bq          -> g_qh_h/l        grid(8, 32)   A 2-pass
// MODE 1: vp = v@Wv^T + bias + loc  -> g_vh_h, g_vhT_h grid(8, 512)  A 1-pass
// MODE 2: score = qh@vh^T * sc      -> attn (fp32)     grid(16, 256) A 2-pass
// MODE 3: out = attn@vh             -> out  (fp32)     grid(256)     A 2-pass
// ---------------------------------------------------------------------------
template <int MODE>
__global__ void __launch_bounds__(256, 2)
mma_gemm(const float* __restrict__ attn_in, const float* __restrict__ biasv,
         const float* __restrict__ la, float* __restrict__ dsto)
{
    extern __shared__ char sm[];
    const uint32_t smb = smem_u32(sm);
    const int t = threadIdx.x, lane = t & 31, w = t >> 5;
    const int wm0 = (w & 3) * 32, wn0 = (w >> 2) * 64;

    constexpr int K   = (MODE < 2) ? HID : (MODE == 2 ? 128 : VL);
    constexpr int NC  = K / 32;
    constexpr int NPA = (MODE == 1) ? 1 : 2;
    constexpr int NT  = (MODE == 1) ? 2 : 3;
    constexpr int BUF = NT * TILE_B;
    constexpr uint32_t BOFF = (uint32_t)(NT - 1) * TILE_B;

    const uint16_t *Ah = nullptr, *Al = nullptr, *Bh = nullptr;
    const float* Afp = nullptr;
    int lda = 0, ldb = 0;
    if (MODE == 0) {
        size_t ao = (size_t)blockIdx.y * 128 * HID, bo = (size_t)blockIdx.x * 128 * HID;
        Ah = s_q_h + ao; Al = s_q_l + ao; Bh = s_Wq_h + bo; lda = ldb = HID;
    } else if (MODE == 1) {
        size_t ao = (size_t)blockIdx.y * 128 * HID, bo = (size_t)blockIdx.x * 128 * HID;
        Ah = s_v_h + ao; Bh = s_Wv_h + bo; lda = ldb = HID;
    } else if (MODE == 2) {
        size_t ao = (size_t)blockIdx.y * QL * 128;
        size_t bo = (size_t)blockIdx.y * VL * 128 + (size_t)blockIdx.x * 128 * 128;
        Ah = g_qh_h + ao; Al = g_qh_l + ao; Bh = g_vh_h + bo; lda = ldb = 128;
    } else {
        Afp = attn_in + (size_t)blockIdx.x * QL * VL;
        Bh  = g_vhT_h + (size_t)blockIdx.x * 128 * VL; ldb = VL;
    }

    float acc[2][8][4];
#pragma unroll
    for (int i = 0; i < 2; i++)
#pragma unroll
        for (int j = 0; j < 8; j++)
#pragma unroll
            for (int k = 0; k < 4; k++) acc[i][j][k] = 0.f;

    auto cp_chunk = [&](int buf, int c) {
        uint32_t sb = smb + buf * BUF;
#pragma unroll
        for (int i = 0; i < NT * 2; i++) {
            int idx = t + 256 * i;
            int tile = idx >> 9, r = (idx >> 2) & 127, s = idx & 3;
            const uint16_t* base; int ld; uint32_t doff;
            if (NT == 2) {
                base = tile ? Bh : Ah; ld = tile ? ldb : lda;
                doff = tile ? TILE_B : 0u;
            } else {
                base = (tile == 0) ? Ah : (tile == 1) ? Al : Bh;
                ld = (tile == 2) ? ldb : lda;
                doff = (uint32_t)tile * TILE_B;
            }
            cp16(sb + doff + r * 80 + s * 16, base + (size_t)r * ld + c * 32 + s * 8);
        }
    };
    auto cp_chunk_b = [&](int buf, int c) {   // MODE 3: B only
        uint32_t sb = smb + buf * BUF + 2 * TILE_B;
#pragma unroll
        for (int i = 0; i < 2; i++) {
            int idx = t + 256 * i;
            int r = (idx >> 2) & 127, s = idx & 3;
            cp16(sb + r * 80 + s * 16, Bh + (size_t)r * ldb + c * 32 + s * 8);
        }
    };

    auto compute = [&](uint32_t sbuf) {
#pragma unroll
        for (int ks = 0; ks < 2; ks++) {
            const uint32_t rowsel = (uint32_t)(lane & 15) * 80
                                  + (uint32_t)((lane >> 4) + ks * 2) * 16;
            uint32_t aH[2][4], bH[4][4];
#pragma unroll
            for (int mt = 0; mt < 2; mt++)
                ldm4(aH[mt], sbuf + (uint32_t)(wm0 + mt * 16) * 80 + rowsel);
#pragma unroll
            for (int g = 0; g < 4; g++)
                ldm4(bH[g], sbuf + BOFF + (uint32_t)(wn0 + g * 16) * 80 + rowsel);
#pragma unroll
            for (int mt = 0; mt < 2; mt++)
#pragma unroll
                for (int g = 0; g < 4; g++) {
                    mma16816(acc[mt][2 * g],     aH[mt], bH[g][0], bH[g][2]);
                    mma16816(acc[mt][2 * g + 1], aH[mt], bH[g][1], bH[g][3]);
                }
            if (NPA == 2) {
                // reuse aH registers for the lo pass
#pragma unroll
                for (int mt = 0; mt < 2; mt++)
                    ldm4(aH[mt], sbuf + TILE_B + (uint32_t)(wm0 + mt * 16) * 80 + rowsel);
#pragma unroll
                for (int mt = 0; mt < 2; mt++)
#pragma unroll
                    for (int g = 0; g < 4; g++) {
                        mma16816(acc[mt][2 * g],     aH[mt], bH[g][0], bH[g][2]);
                        mma16816(acc[mt][2 * g + 1], aH[mt], bH[g][1], bH[g][3]);
                    }
            }
        }
    };

    // MODE 3 A-operand register path (fp32 attn -> fp16 split in-kernel)
    float4 arg[4];
    const float* ap3 = (MODE == 3) ? Afp + (size_t)(t >> 1) * VL + (t & 1) * 16 : nullptr;
    const uint32_t aoff3 = (t >> 1) * 80 + (t & 1) * 32;

#define LD_A3(c)  { _Pragma("unroll") for (int j = 0; j < 4; j++) arg[j] = *(const float4*)(ap3 + (c) * 32 + j * 4); }
#define STS_A3(buf) { \
        char* bb = sm + (buf) * BUF;                                          \
        uint4 H, L;                                                           \
        H.x = sp2h(arg[0].x, arg[0].y, L.x); H.y = sp2h(arg[0].z, arg[0].w, L.y); \
        H.z = sp2h(arg[1].x, arg[1].y, L.z); H.w = sp2h(arg[1].z, arg[1].w, L.w); \
        *(uint4*)(bb + aoff3) = H; *(uint4*)(bb + TILE_B + aoff3) = L;        \
        H.x = sp2h(arg[2].x, arg[2].y, L.x); H.y = sp2h(arg[2].z, arg[2].w, L.y); \
        H.z = sp2h(arg[3].x, arg[3].y, L.z); H.w = sp2h(arg[3].z, arg[3].w, L.w); \
        *(uint4*)(bb + aoff3 + 16) = H; *(uint4*)(bb + TILE_B + aoff3 + 16) = L; }

    if (MODE == 3) {
        LD_A3(0); STS_A3(0);
        LD_A3(1); STS_A3(1);
        LD_A3(2); STS_A3(2);
        LD_A3(3);
        cp_chunk_b(0, 0); CP_COMMIT();
        cp_chunk_b(1, 1); CP_COMMIT();
        cp_chunk_b(2, 2); CP_COMMIT();
    } else {
        cp_chunk(0, 0); CP_COMMIT();
        cp_chunk(1, 1); CP_COMMIT();
        cp_chunk(2, 2); CP_COMMIT();
    }

    int buf = 0;
    for (int c = 0; c < NC; c++) {
        CP_WAIT2();
        __syncthreads();
        compute(smb + buf * BUF);
        __syncthreads();
        if (c + 3 < NC) {
            if (MODE == 3) {
                STS_A3(buf);
                cp_chunk_b(buf, c + 3);
            } else {
                cp_chunk(buf, c + 3);
            }
        }
        CP_COMMIT();
        if (MODE == 3 && c + 4 < NC) LD_A3(c + 4);
        buf = (buf == 2) ? 0 : buf + 1;
    }

    // ------------------------- epilogue -------------------------
    float* vec = (float*)(sm + 34048);
    if (MODE == 0) {
        if (t < 128) vec[t] = biasv[blockIdx.x * 128 + t];
    }
    if (MODE == 1) {
        if (t < 128) {
            vec[t]       = biasv[blockIdx.x * 128 + t] + g_Cc[t];
            vec[128 + t] = g_A0[t];
            vec[256 + t] = g_A1[t];
            vec[384 + t] = g_A2[t];
        }
        const int b = blockIdx.y >> 4, h = blockIdx.x;
        const int vpos0 = (blockIdx.y & 15) * 128;
        const float* lar = la + (size_t)(b * 8 + h) * VL;
        if (t < 130) {
            int g = vpos0 - 1 + t;
            vec[512 + t] = (g >= 0 && g < VL) ? lar[g] : 0.f;
        }
    }
    __syncthreads();

#pragma unroll
    for (int mt = 0; mt < 2; mt++) {
#pragma unroll
        for (int h2 = 0; h2 < 2; h2++) {
            const int row = wm0 + mt * 16 + (lane >> 2) + h2 * 8;
            size_t obase = 0;
            float* dst = nullptr;
            float lm1 = 0.f, l0 = 0.f, lp1 = 0.f;
            if (MODE == 0) {
                obase = (((size_t)(blockIdx.x * 32 + blockIdx.y)) * QL + row) * 128;
            } else if (MODE == 1) {
                int b = blockIdx.y >> 4, h = blockIdx.x;
                int vpos0 = (blockIdx.y & 15) * 128;
                lm1 = vec[512 + row]; l0 = vec[513 + row]; lp1 = vec[514 + row];
                obase = (((size_t)(h * 32 + b)) * VL + vpos0 + row) * 128;
            } else if (MODE == 2) {
                dst = dsto + ((size_t)blockIdx.y * QL + row) * VL + blockIdx.x * 128;
            } else {
                int h = blockIdx.x >> 5, b = blockIdx.x & 31;
                dst = dsto + ((size_t)(b * QL + row)) * HID + h * 128;
            }
#pragma unroll
            for (int nt = 0; nt < 8; nt++) {
                const int col = wn0 + nt * 8 + 2 * (lane & 3);
                float x = acc[mt][nt][2 * h2];
                float y = acc[mt][nt][2 * h2 + 1];
                if (MODE == 0) {
                    x += vec[col]; y += vec[col + 1];
                    uint32_t lo, hi = sp2h(x, y, lo);
                    *(uint32_t*)&g_qh_h[obase + col] = hi;
                    *(uint32_t*)&g_qh_l[obase + col] = lo;
                } else if (MODE == 1) {
                    x += vec[col]     + vec[128 + col]     * lm1 + vec[256 + col]     * l0 + vec[384 + col]     * lp1;
                    y += vec[col + 1] + vec[128 + col + 1] * lm1 + vec[256 + col + 1] * l0 + vec[384 + col + 1] * lp1;
                    uint32_t hi = pk2h(x, y);
                    *(uint32_t*)&g_vh_h[obase + col] = hi;
                    *(uint32_t*)(sm + (row * 65 + (col >> 1)) * 4) = hi;
                } else if (MODE == 2) {
                    const float sc = 0.08838834764831845f;
                    *(float2*)(dst + col) = make_float2(x * sc, y * sc);
                } else {
                    *(float2*)(dst + col) = make_float2(x, y);
                }
            }
        }
    }

    if (MODE == 1) {
        __syncthreads();
        const int b = blockIdx.y >> 4, h = blockIdx.x;
        const int vpos0 = (blockIdx.y & 15) * 128;
        const int d = t >> 1, vh2 = t & 1;
        size_t ob = (((size_t)(h * 32 + b)) * 128 + d) * VL + vpos0 + vh2 * 64;
#pragma unroll
        for (int blk = 0; blk < 8; blk++) {
            uint16_t e[8];
#pragma unroll
            for (int j = 0; j < 8; j++) {
                int v = vh2 * 64 + blk * 8 + j;
                e[j] = *(uint16_t*)(sm + (v * 65 + (d >> 1)) * 4 + (d & 1) * 2);
            }
            uint4 o;
            o.x = (uint32_t)e[0] | ((uint32_t)e[1] << 16);
            o.y = (uint32_t)e[2] | ((uint32_t)e[3] << 16);
            o.z = (uint32_t)e[4] | ((uint32_t)e[5] << 16);
            o.w = (uint32_t)e[6] | ((uint32_t)e[7] << 16);
            *(uint4*)&g_vhT_h[ob + blk * 8] = o;
        }
    }
}

// ---------------------------------------------------------------------------
DI void split_body(const float4* __restrict__ in, uint16_t* oh, uint16_t* ol, int n4) {
    int i = blockIdx.x * 256 + threadIdx.x;
    if (i >= n4) return;
    float4 x = in[i];
    uint32_t l0, l1;
    uint32_t h0 = sp2h(x.x, x.y, l0), h1 = sp2h(x.z, x.w, l1);
    uint2 H; H.x = h0; H.y = h1;
    *(uint2*)&oh[(size_t)i * 4] = H;
    if (ol) { uint2 L; L.x = l0; L.y = l1; *(uint2*)&ol[(size_t)i * 4] = L; }
}
__global__ void split_q_k(const float4* in)  { split_body(in, s_q_h, s_q_l, 1048576); }
__global__ void split_v_k(const float4* in)  { split_body(in, s_v_h, nullptr, 16777216); }
__global__ void split_wq_k(const float4* in) { split_body(in, s_Wq_h, nullptr, 262144); }
__global__ void split_wv_k(const float4* in) { split_body(in, s_Wv_h, nullptr, 262144); }

// ---------------------------------------------------------------------------
__global__ void prep_kernel(const float* __restrict__ conv_w,
                            const float* __restrict__ conv_b,
                            const float* __restrict__ Wloc)
{
    int d = threadIdx.x;
    float a0 = 0.f, a1 = 0.f, a2 = 0.f, c = 0.f;
#pragma unroll
    for (int cc = 0; cc < 10; cc++) {
        float wl = Wloc[d * 10 + cc];
        a0 += wl * conv_w[cc * 3 + 0];
        a1 += wl * conv_w[cc * 3 + 1];
        a2 += wl * conv_w[cc * 3 + 2];
        c  += wl * conv_b[cc];
    }
    g_A0[d] = a0; g_A1[d] = a1; g_A2[d] = a2; g_Cc[d] = c;
}

// ---------------------------------------------------------------------------
__global__ void __launch_bounds__(256) softmax_kernel(float* __restrict__ attn)
{
    __shared__ float sm1[8], sm2[8];
    const size_t base = (size_t)blockIdx.x * VL;
    const int t = threadIdx.x, lane = t & 31, w = t >> 5;
    float4 a = *(float4*)(attn + base + t * 4);
    float4 b = *(float4*)(attn + base + 1024 + t * 4);
    float m = fmaxf(fmaxf(fmaxf(a.x, a.y), fmaxf(a.z, a.w)),
                    fmaxf(fmaxf(b.x, b.y), fmaxf(b.z, b.w)));
#pragma unroll
    for (int s = 16; s; s >>= 1) m = fmaxf(m, __shfl_xor_sync(~0u, m, s));
    if (lane == 0) sm1[w] = m;
    __syncthreads();
    m = sm1[0];
#pragma unroll
    for (int i = 1; i < 8; i++) m = fmaxf(m, sm1[i]);
    a.x = __expf(a.x - m); a.y = __expf(a.y - m); a.z = __expf(a.z - m); a.w = __expf(a.w - m);
    b.x = __expf(b.x - m); b.y = __expf(b.y - m); b.z = __expf(b.z - m); b.w = __expf(b.w - m);
    float s = a.x + a.y + a.z + a.w + b.x + b.y + b.z + b.w;
#pragma unroll
    for (int sh = 16; sh; sh >>= 1) s += __shfl_xor_sync(~0u, s, sh);
    if (lane == 0) sm2[w] = s;
    __syncthreads();
    s = sm2[0];
#pragma unroll
    for (int i = 1; i < 8; i++) s += sm2[i];
    float inv = 1.0f / s;
    a.x *= inv; a.y *= inv; a.z *= inv; a.w *= inv;
    b.x *= inv; b.y *= inv; b.z *= inv; b.w *= inv;
    *(float4*)(attn + base + t * 4) = a;
    *(float4*)(attn + base + 1024 + t * 4) = b;
}

// ---------------------------------------------------------------------------
extern "C" void kernel_launch(void* const* d_in, const int* in_sizes, int n_in,
                              void* d_out, int out_size)
{
    const float* q         = (const float*)d_in[0];
    const float* v         = (const float*)d_in[1];
    const float* last_attn = (const float*)d_in[2];
    const float* conv_w    = (const float*)d_in[3];
    const float* conv_b    = (const float*)d_in[4];
    const float* Wq        = (const float*)d_in[5];
    const float* bq        = (const float*)d_in[6];
    const float* Wv        = (const float*)d_in[7];
    const float* Wloc      = (const float*)d_in[8];
    const float* bias      = (const float*)d_in[9];

    float* out  = (float*)d_out;
    float* attn = out + 4194304;

    const int SM3 = 3 * 3 * TILE_B;   // 92160 (modes 0/2/3)
    const int SM2 = 3 * 2 * TILE_B;   // 61440 (mode 1)

    static bool attr_done = false;
    if (!attr_done) {
        cudaFuncSetAttribute(mma_gemm<0>, cudaFuncAttributeMaxDynamicSharedMemorySize, SM3);
        cudaFuncSetAttribute(mma_gemm<1>, cudaFuncAttributeMaxDynamicSharedMemorySize, SM2);
        cudaFuncSetAttribute(mma_gemm<2>, cudaFuncAttributeMaxDynamicSharedMemorySize, SM3);
        cudaFuncSetAttribute(mma_gemm<3>, cudaFuncAttributeMaxDynamicSharedMemorySize, SM3);
        attr_done = true;
    }

    prep_kernel<<<1, 128>>>(conv_w, conv_b, Wloc);
    split_q_k <<<4096,  256>>>((const float4*)q);
    split_v_k <<<65536, 256>>>((const float4*)v);
    split_wq_k<<<1024,  256>>>((const float4*)Wq);
    split_wv_k<<<1024,  256>>>((const float4*)Wv);

    mma_gemm<0><<<dim3(8, 32),   256, SM3>>>(nullptr, bq,   nullptr,   nullptr);
    mma_gemm<1><<<dim3(8, 512),  256, SM2>>>(nullptr, bias, last_attn, nullptr);
    mma_gemm<2><<<dim3(16, 256), 256, SM3>>>(nullptr, nullptr, nullptr, attn);
    softmax_kernel<<<32768, 256>>>(attn);
    mma_gemm<3><<<256, 256, SM3>>>(attn, nullptr, nullptr, out);
}